// round 7
// baseline (speedup 1.0000x reference)
#include <cuda_runtime.h>
#include <cuda_bf16.h>
#include <cstdint>

// Problem constants
#define NN 16384
#define DD 1024
#define CC 1024
#define EPSV 1e-6f
#define DEN_EPS 1e-5f

// ---------------- device scratch ---------------------------------------------
__device__ __align__(1024) __nv_bfloat16 g_fb[NN * DD];   // features bf16 (32MB)
__device__ __align__(1024) __nv_bfloat16 g_cb[CC * DD];   // centers  bf16 ( 2MB)
__device__ float g_rowterm[NN];
__device__ float g_centerterm[CC];
__device__ int   g_minmap[NN];
__device__ int   g_odd_nonzero = 0;

// ---------------- helpers -------------------------------------------------------
__device__ __forceinline__ int fmap(float f) {
    int i = __float_as_int(f);
    return i >= 0 ? i : (i ^ 0x7FFFFFFF);
}
__device__ __forceinline__ float funmap(int i) {
    return __int_as_float(i >= 0 ? i : (i ^ 0x7FFFFFFF));
}

__device__ __forceinline__ void cp16(void* dst, const void* src) {
    unsigned d = (unsigned)__cvta_generic_to_shared(dst);
    asm volatile("cp.async.cg.shared.global [%0], [%1], 16;\n" :: "r"(d), "l"(src) : "memory");
}
__device__ __forceinline__ void cp_commit() {
    asm volatile("cp.async.commit_group;\n" ::: "memory");
}
template <int N>
__device__ __forceinline__ void cp_wait() {
    asm volatile("cp.async.wait_group %0;\n" :: "n"(N) : "memory");
}

__device__ __forceinline__ void ldm_x4(uint32_t* r, uint32_t saddr) {
    asm volatile("ldmatrix.sync.aligned.m8n8.x4.shared.b16 {%0,%1,%2,%3}, [%4];\n"
                 : "=r"(r[0]), "=r"(r[1]), "=r"(r[2]), "=r"(r[3]) : "r"(saddr));
}

__device__ __forceinline__ void mma16816(float* c, const uint32_t* a,
                                         uint32_t b0, uint32_t b1) {
    asm volatile(
        "mma.sync.aligned.m16n8k16.row.col.f32.bf16.bf16.f32 "
        "{%0,%1,%2,%3}, {%4,%5,%6,%7}, {%8,%9}, {%0,%1,%2,%3};\n"
        : "+f"(c[0]), "+f"(c[1]), "+f"(c[2]), "+f"(c[3])
        : "r"(a[0]), "r"(a[1]), "r"(a[2]), "r"(a[3]), "r"(b0), "r"(b1));
}

// ---------------- fused prologue ------------------------------------------------
__device__ __forceinline__ void prep_rows(const float* __restrict__ src,
                                          __nv_bfloat16* dst, float* term,
                                          int blk, float coef, float add) {
    int wid  = threadIdx.x >> 5;
    int lane = threadIdx.x & 31;
    int row  = blk * 8 + wid;

    const float4* s4 = reinterpret_cast<const float4*>(src + (size_t)row * DD);
    uint2* d2 = reinterpret_cast<uint2*>(dst + (size_t)row * DD);

    float s = 0.f, s2 = 0.f;
    #pragma unroll
    for (int i = 0; i < 8; i++) {
        float4 v = s4[i * 32 + lane];
        __nv_bfloat162 lo = __floats2bfloat162_rn(v.x, v.y);
        __nv_bfloat162 hi = __floats2bfloat162_rn(v.z, v.w);
        uint2 packed;
        packed.x = *reinterpret_cast<uint32_t*>(&lo);
        packed.y = *reinterpret_cast<uint32_t*>(&hi);
        d2[i * 32 + lane] = packed;
        s  += v.x + v.y + v.z + v.w;
        s2 += v.x * v.x + v.y * v.y + v.z * v.z + v.w * v.w;
    }
    #pragma unroll
    for (int off = 16; off; off >>= 1) {
        s  += __shfl_xor_sync(0xffffffff, s,  off);
        s2 += __shfl_xor_sync(0xffffffff, s2, off);
    }
    if (lane == 0) term[row] = s2 + coef * s + add;
}

__global__ void __launch_bounds__(256) prologue_kernel(
        const float* __restrict__ f, const float* __restrict__ c,
        const unsigned int* __restrict__ lw) {
    int b = blockIdx.x;
    if (b < 2048) {
        prep_rows(f, g_fb, g_rowterm, b, 2.0f * EPSV, EPSV * EPSV * (float)DD);
    } else if (b < 2176) {
        prep_rows(c, g_cb, g_centerterm, b - 2048, -2.0f * EPSV, 0.0f);
    } else {
        int i = (b - 2176) * 256 + threadIdx.x;   // [0, 16384)
        g_minmap[i] = 0x7F800000;                 // fmap(+inf)
        if ((i & 1) && lw[i] != 0u) atomicOr(&g_odd_nonzero, 1);
    }
}

// ---------------- persistent GEMM + min epilogue ---------------------------------
// CTA tile 128x128, BK=64, 3-stage cp.async pipeline that never drains across
// tile boundaries. 4 warps (2m x 2n), warp tile 64x64. 2 CTAs/SM.
#define BM 128
#define BN 128
#define BK 64
#define KITER 16                // DD / BK, k-iterations per tile
#define NTILES (NN / BM * CC / BN)   // 1024
#define A_BYTES (BM * BK * 2)   // 16384
#define B_BYTES (BN * BK * 2)   // 16384
#define STAGE_BYTES (A_BYTES + B_BYTES)
#define STAGES 3
#define GEMM_SMEM (STAGES * STAGE_BYTES + 16)
#define NTHREADS 128

// swizzled byte offset for (row, kbyte) — loader-side (not hot)
__device__ __forceinline__ uint32_t swz(int r, int kbyte) {
    return (uint32_t)(r * 128 + (((kbyte >> 4) ^ (r & 7)) << 4) + (kbyte & 15));
}

__global__ void __launch_bounds__(NTHREADS, 2) gemm_min_kernel() {
    extern __shared__ char sm_raw[];
    char* smb = sm_raw;

    const int tid  = threadIdx.x;
    const int lane = tid & 31;
    const int wid  = tid >> 5;       // 0..3
    const int wm   = wid >> 1;       // 0..1
    const int wn   = wid & 1;        // 0..1
    const int bid  = blockIdx.x;
    const int G    = gridDim.x;

    const int ntiles = (NTILES - bid + G - 1) / G;
    const int total  = ntiles * KITER;

    const uint32_t smem0 = (uint32_t)__cvta_generic_to_shared(smb);

    // ---- XOR-folded LDSM base offsets (within a stage tile) ----
    uint32_t aB[4], bB[4];
    {
        uint32_t hi16 = ((lane >> 4) & 1) << 4;
        #pragma unroll
        for (int mt = 0; mt < 4; mt++) {
            int r = wm * 64 + mt * 16 + (lane & 15);
            aB[mt] = ((uint32_t)(r * 128) | (uint32_t)((r & 7) << 4)) ^ hi16;
        }
        uint32_t hib = ((lane >> 3) & 1) << 4;
        #pragma unroll
        for (int p = 0; p < 4; p++) {
            int r = wn * 64 + p * 16 + (lane & 7) + ((lane & 16) >> 1);
            bB[p] = ((uint32_t)(r * 128) | (uint32_t)((r & 7) << 4)) ^ hib;
        }
    }

    float acc[4][8][4];
    #pragma unroll
    for (int mt = 0; mt < 4; mt++)
        #pragma unroll
        for (int nt = 0; nt < 8; nt++)
            #pragma unroll
            for (int j = 0; j < 4; j++) acc[mt][nt][j] = 0.f;

    // stage loader for flattened iteration index 'it'
    auto stage = [&](int it) {
        int t   = bid + (it >> 4) * G;          // global tile
        int kt  = it & 15;
        const __nv_bfloat16* Ag = g_fb + (size_t)(t >> 3) * BM * DD + kt * BK;
        const __nv_bfloat16* Bg = g_cb + (size_t)(t & 7) * BN * DD + kt * BK;
        char* As = smb + (it % STAGES) * STAGE_BYTES;
        char* Bs = As + A_BYTES;
        #pragma unroll
        for (int i = 0; i < 8; i++) {
            int idx = tid + i * NTHREADS;
            int r = idx >> 3, c = idx & 7;
            cp16(As + swz(r, c * 16), Ag + (size_t)r * DD + c * 8);
        }
        #pragma unroll
        for (int i = 0; i < 8; i++) {
            int idx = tid + i * NTHREADS;
            int r = idx >> 3, c = idx & 7;
            cp16(Bs + swz(r, c * 16), Bg + (size_t)r * DD + c * 8);
        }
        cp_commit();
    };

    stage(0);
    stage(1);

    for (int it = 0; it < total; it++) {
        if (it < total - 1) cp_wait<1>(); else cp_wait<0>();
        __syncthreads();

        const uint32_t a_base = smem0 + (uint32_t)((it % STAGES) * STAGE_BYTES);
        const uint32_t b_base = a_base + A_BYTES;

        // ks = 0: LDSMs first so the tensor pipe refills right after the barrier
        uint32_t a[4][4], b[4][4];
        #pragma unroll
        for (int mt = 0; mt < 4; mt++) ldm_x4(a[mt], a_base + aB[mt]);
        #pragma unroll
        for (int p = 0; p < 4; p++)  ldm_x4(b[p],  b_base + bB[p]);

        if (it + 2 < total) stage(it + 2);   // prefetch (possibly next tile)

        #pragma unroll
        for (int mt = 0; mt < 4; mt++)
            #pragma unroll
            for (int p = 0; p < 4; p++) {
                mma16816(acc[mt][2 * p],     a[mt], b[p][0], b[p][1]);
                mma16816(acc[mt][2 * p + 1], a[mt], b[p][2], b[p][3]);
            }

        #pragma unroll
        for (int ks = 1; ks < 4; ks++) {
            const uint32_t kx = (uint32_t)(ks * 32);
            #pragma unroll
            for (int mt = 0; mt < 4; mt++) ldm_x4(a[mt], a_base + (aB[mt] ^ kx));
            #pragma unroll
            for (int p = 0; p < 4; p++)  ldm_x4(b[p],  b_base + (bB[p] ^ kx));
            #pragma unroll
            for (int mt = 0; mt < 4; mt++)
                #pragma unroll
                for (int p = 0; p < 4; p++) {
                    mma16816(acc[mt][2 * p],     a[mt], b[p][0], b[p][1]);
                    mma16816(acc[mt][2 * p + 1], a[mt], b[p][2], b[p][3]);
                }
        }

        // ---- tile boundary: fused min epilogue (overlaps in-flight prefetch) ----
        if ((it & 15) == 15) {
            int t    = bid + (it >> 4) * G;
            int brow = (t >> 3) * BM;
            int bcol = (t & 7) * BN;

            const float* ctp = g_centerterm + bcol + wn * 64 + (lane & 3) * 2;
            float ct0[8], ct1[8];
            #pragma unroll
            for (int nt = 0; nt < 8; nt++) {
                ct0[nt] = __ldg(ctp + nt * 8);
                ct1[nt] = __ldg(ctp + nt * 8 + 1);
            }

            #pragma unroll
            for (int mt = 0; mt < 4; mt++) {
                float m0 = 1e30f, m1 = 1e30f;
                #pragma unroll
                for (int nt = 0; nt < 8; nt++) {
                    m0 = fminf(m0, fminf(fmaf(-2.f, acc[mt][nt][0], ct0[nt]),
                                         fmaf(-2.f, acc[mt][nt][1], ct1[nt])));
                    m1 = fminf(m1, fminf(fmaf(-2.f, acc[mt][nt][2], ct0[nt]),
                                         fmaf(-2.f, acc[mt][nt][3], ct1[nt])));
                    acc[mt][nt][0] = 0.f; acc[mt][nt][1] = 0.f;
                    acc[mt][nt][2] = 0.f; acc[mt][nt][3] = 0.f;
                }
                #pragma unroll
                for (int off = 1; off < 4; off <<= 1) {
                    m0 = fminf(m0, __shfl_xor_sync(0xffffffff, m0, off));
                    m1 = fminf(m1, __shfl_xor_sync(0xffffffff, m1, off));
                }
                if ((lane & 3) == 0) {
                    int r = brow + wm * 64 + mt * 16 + (lane >> 2);
                    atomicMin(&g_minmap[r],     fmap(m0));
                    atomicMin(&g_minmap[r + 8], fmap(m1));
                }
            }
        }
    }
}

// ---------------- fused masked reduction (single block) ---------------------------
__global__ void __launch_bounds__(1024) reduce_final_kernel(
        const void* __restrict__ labels, float* __restrict__ out) {
    int tid = threadIdx.x;
    bool lab64 = (g_odd_nonzero == 0);

    float s = 0.f, c = 0.f;
    #pragma unroll
    for (int i = 0; i < 16; i++) {
        int row = tid + i * 1024;
        float m    = funmap(g_minmap[row]);
        float sq   = g_rowterm[row] + m;
        float dist = sqrtf(fmaxf(sq, 0.f));
        long long lab = lab64 ? ((const long long*)labels)[row]
                              : (long long)((const int*)labels)[row];
        if (lab == 0) { s += dist; c += 1.f; }
    }
    #pragma unroll
    for (int off = 16; off; off >>= 1) {
        s += __shfl_xor_sync(0xffffffff, s, off);
        c += __shfl_xor_sync(0xffffffff, c, off);
    }
    __shared__ float sh[2][32];
    int w = tid >> 5, l = tid & 31;
    if (l == 0) { sh[0][w] = s; sh[1][w] = c; }
    __syncthreads();
    if (w == 0) {
        float ts = sh[0][l], tc = sh[1][l];
        #pragma unroll
        for (int off = 16; off; off >>= 1) {
            ts += __shfl_xor_sync(0xffffffff, ts, off);
            tc += __shfl_xor_sync(0xffffffff, tc, off);
        }
        if (l == 0) out[0] = ts / (tc + DEN_EPS);
    }
}

// ---------------- launch -------------------------------------------------------------
extern "C" void kernel_launch(void* const* d_in, const int* in_sizes, int n_in,
                              void* d_out, int out_size) {
    const float* features = (const float*)d_in[0];
    const void*  labels   = d_in[1];
    const float* centers  = (const float*)d_in[2];
    float* out = (float*)d_out;

    static int nsm = 0;
    if (nsm == 0) cudaDeviceGetAttribute(&nsm, cudaDevAttrMultiProcessorCount, 0);
    int grid = 2 * nsm;
    if (grid <= 0 || grid > NTILES) grid = 296;

    cudaFuncSetAttribute(gemm_min_kernel,
                         cudaFuncAttributeMaxDynamicSharedMemorySize, GEMM_SMEM);

    prologue_kernel<<<2240, 256>>>(features, centers, (const unsigned int*)labels);
    gemm_min_kernel<<<grid, NTHREADS, GEMM_SMEM>>>();
    reduce_final_kernel<<<1, 1024>>>(labels, out);
}